// round 1
// baseline (speedup 1.0000x reference)
#include <cuda_runtime.h>
#include <math.h>
#include <stdint.h>

// Problem constants
#define BB 4
#define SS 2048
#define UU 1024
#define HH 8
#define HD 128
#define NHEAD (BB*HH)          // 32
#define MROWS (BB*SS)          // 8192
#define LN_EPS 1e-8f

// Scratch (device globals: allocation-free rule)
__device__ float g_q[(size_t)MROWS * UU];
__device__ float g_k[(size_t)MROWS * UU];
__device__ float g_v[(size_t)MROWS * UU];
__device__ float g_r[(size_t)MROWS * UU];
__device__ float g_attn[(size_t)MROWS * UU];
__device__ float g_scores[(size_t)NHEAD * SS * SS];   // 512 MB

// ---------------------------------------------------------------------------
// Tiled SGEMM: 128x128 block tile, BK=16, 8x8 per-thread tile, 256 threads.
// MODE 0: C = relu(A @ B + bias)           (A[M,K] NN, B[K,N])
// MODE 1: C = alpha * (A @ B^T)            (B row-major [N,K])
// MODE 2: C = A @ B                        (NN)
// All of M, N, K are multiples of the tile sizes for this problem.
// ---------------------------------------------------------------------------
#define BM 128
#define BN 128
#define BKK 16
#define TM 8
#define TN 8

template<int MODE>
__global__ __launch_bounds__(256)
void sgemm_kernel(const float* __restrict__ A, const float* __restrict__ B,
                  const float* __restrict__ bias, float* __restrict__ C,
                  int M, int N, int K, float alpha,
                  size_t aBatch, size_t bBatch, size_t cBatch)
{
    __shared__ float As[BKK][BM];
    __shared__ float Bs[BKK][BN + 8];   // +8 keeps float4 smem stores 16B-aligned

    const int tid  = threadIdx.x;
    const int tcol = tid & 15;          // 0..15
    const int trow = tid >> 4;          // 0..15
    const int z    = blockIdx.z;

    const float* Ab = A + aBatch * (size_t)z + (size_t)blockIdx.y * BM * K;
    const float* Bb = B + bBatch * (size_t)z;
    float*       Cb = C + cBatch * (size_t)z;

    float acc[TM][TN];
#pragma unroll
    for (int i = 0; i < TM; i++)
#pragma unroll
        for (int j = 0; j < TN; j++) acc[i][j] = 0.f;

    float ar[TM], br[TN];

    for (int kt = 0; kt < K; kt += BKK) {
        // ---- load A tile (128 x 16), store transposed As[k][m]
#pragma unroll
        for (int it = 0; it < 2; it++) {
            int idx = tid + it * 256;            // 0..511
            int m   = idx >> 2;                  // 0..127
            int kq  = (idx & 3) * 4;             // 0,4,8,12
            float4 va = *(const float4*)(Ab + (size_t)m * K + kt + kq);
            As[kq + 0][m] = va.x;
            As[kq + 1][m] = va.y;
            As[kq + 2][m] = va.z;
            As[kq + 3][m] = va.w;
        }
        // ---- load B tile
        if (MODE == 1) {
            // NT: B rows are the N dim; tile [BN][BK] -> Bs[k][n]
            const float* Bt = Bb + (size_t)blockIdx.x * BN * K;
#pragma unroll
            for (int it = 0; it < 2; it++) {
                int idx = tid + it * 256;
                int n   = idx >> 2;
                int kq  = (idx & 3) * 4;
                float4 vb = *(const float4*)(Bt + (size_t)n * K + kt + kq);
                Bs[kq + 0][n] = vb.x;
                Bs[kq + 1][n] = vb.y;
                Bs[kq + 2][n] = vb.z;
                Bs[kq + 3][n] = vb.w;
            }
        } else {
            // NN: tile [BK][BN] row-major
#pragma unroll
            for (int it = 0; it < 2; it++) {
                int idx = tid + it * 256;
                int kr  = idx >> 5;                   // 0..15
                int n4  = (idx & 31) * 4;             // 0..124
                float4 vb = *(const float4*)(Bb + (size_t)(kt + kr) * N
                                             + (size_t)blockIdx.x * BN + n4);
                *(float4*)&Bs[kr][n4] = vb;
            }
        }
        __syncthreads();

#pragma unroll
        for (int k = 0; k < BKK; k++) {
#pragma unroll
            for (int i = 0; i < TM; i++) ar[i] = As[k][trow * TM + i];
#pragma unroll
            for (int j = 0; j < TN; j++) br[j] = Bs[k][tcol * TN + j];
#pragma unroll
            for (int i = 0; i < TM; i++)
#pragma unroll
                for (int j = 0; j < TN; j++) acc[i][j] = fmaf(ar[i], br[j], acc[i][j]);
        }
        __syncthreads();
    }

    // ---- epilogue
    const int row0 = blockIdx.y * BM + trow * TM;
    const int col0 = blockIdx.x * BN + tcol * TN;
#pragma unroll
    for (int i = 0; i < TM; i++) {
#pragma unroll
        for (int j4 = 0; j4 < TN; j4 += 4) {
            float4 r;
            float vv[4];
#pragma unroll
            for (int j = 0; j < 4; j++) {
                float val = acc[i][j4 + j];
                if (MODE == 0) val = fmaxf(val + bias[col0 + j4 + j], 0.f);
                if (MODE == 1) val *= alpha;
                vv[j] = val;
            }
            r.x = vv[0]; r.y = vv[1]; r.z = vv[2]; r.w = vv[3];
            *(float4*)(Cb + (size_t)(row0 + i) * N + col0 + j4) = r;
        }
    }
}

// ---------------------------------------------------------------------------
// Row softmax over 2048 columns: one block (256 threads) per row.
// ---------------------------------------------------------------------------
__global__ __launch_bounds__(256)
void softmax_kernel(float* __restrict__ sc)
{
    const int tid = threadIdx.x;
    float* row = sc + (size_t)blockIdx.x * SS;

    float x[8];
    float m = -1e30f;
#pragma unroll
    for (int i = 0; i < 8; i++) {
        x[i] = row[tid + i * 256];
        m = fmaxf(m, x[i]);
    }
#pragma unroll
    for (int o = 16; o > 0; o >>= 1) m = fmaxf(m, __shfl_xor_sync(0xffffffffu, m, o));
    __shared__ float sm[8];
    if ((tid & 31) == 0) sm[tid >> 5] = m;
    __syncthreads();
    m = sm[0];
#pragma unroll
    for (int i = 1; i < 8; i++) m = fmaxf(m, sm[i]);

    float s = 0.f;
#pragma unroll
    for (int i = 0; i < 8; i++) { x[i] = __expf(x[i] - m); s += x[i]; }
#pragma unroll
    for (int o = 16; o > 0; o >>= 1) s += __shfl_xor_sync(0xffffffffu, s, o);
    __shared__ float ss[8];
    if ((tid & 31) == 0) ss[tid >> 5] = s;
    __syncthreads();
    s = 0.f;
#pragma unroll
    for (int i = 0; i < 8; i++) s += ss[i];

    const float inv = 1.0f / s;
#pragma unroll
    for (int i = 0; i < 8; i++) row[tid + i * 256] = x[i] * inv;
}

// ---------------------------------------------------------------------------
// Fused epilogue: out = gamma * LN(relu(attn + res)) + beta
// One block (256 threads) per row of 1024.
// ---------------------------------------------------------------------------
__device__ __forceinline__ float block_sum_256(float v, float* sh)
{
#pragma unroll
    for (int o = 16; o > 0; o >>= 1) v += __shfl_xor_sync(0xffffffffu, v, o);
    if ((threadIdx.x & 31) == 0) sh[threadIdx.x >> 5] = v;
    __syncthreads();
    float t = 0.f;
#pragma unroll
    for (int i = 0; i < 8; i++) t += sh[i];
    __syncthreads();
    return t;
}

__global__ __launch_bounds__(256)
void ln_kernel(const float* __restrict__ attn, const float* __restrict__ res,
               const float* __restrict__ gamma, const float* __restrict__ beta,
               float* __restrict__ out)
{
    __shared__ float sh[8];
    const int tid = threadIdx.x;
    const size_t base = (size_t)blockIdx.x * UU;

    float v[4];
    float s = 0.f;
#pragma unroll
    for (int i = 0; i < 4; i++) {
        int c = tid + i * 256;
        float t = attn[base + c] + res[base + c];
        t = fmaxf(t, 0.f);
        v[i] = t;
        s += t;
    }
    const float mean = block_sum_256(s, sh) * (1.0f / UU);

    float vs = 0.f;
#pragma unroll
    for (int i = 0; i < 4; i++) {
        float d = v[i] - mean;
        vs += d * d;
    }
    const float var = block_sum_256(vs, sh) * (1.0f / UU);
    const float inv = rsqrtf(var + LN_EPS);

#pragma unroll
    for (int i = 0; i < 4; i++) {
        int c = tid + i * 256;
        out[base + c] = gamma[c] * ((v[i] - mean) * inv) + beta[c];
    }
}

// ---------------------------------------------------------------------------
extern "C" void kernel_launch(void* const* d_in, const int* in_sizes, int n_in,
                              void* d_out, int out_size)
{
    const float* x     = (const float*)d_in[0];
    const float* Wq    = (const float*)d_in[1];
    const float* bq    = (const float*)d_in[2];
    const float* Wk    = (const float*)d_in[3];
    const float* bk    = (const float*)d_in[4];
    const float* Wv    = (const float*)d_in[5];
    const float* bv    = (const float*)d_in[6];
    const float* Wr    = (const float*)d_in[7];
    const float* br_   = (const float*)d_in[8];
    const float* gamma = (const float*)d_in[9];
    const float* beta  = (const float*)d_in[10];
    float* out = (float*)d_out;

    float *q, *k, *v, *r, *attn, *sc;
    cudaGetSymbolAddress((void**)&q,    g_q);
    cudaGetSymbolAddress((void**)&k,    g_k);
    cudaGetSymbolAddress((void**)&v,    g_v);
    cudaGetSymbolAddress((void**)&r,    g_r);
    cudaGetSymbolAddress((void**)&attn, g_attn);
    cudaGetSymbolAddress((void**)&sc,   g_scores);

    // 1) Four projection GEMMs: [8192,1024] @ [1024,1024] + bias, ReLU
    {
        dim3 grid(UU / BN, MROWS / BM, 1);
        sgemm_kernel<0><<<grid, 256>>>(x, Wq, bq,  q, MROWS, UU, UU, 1.f, 0, 0, 0);
        sgemm_kernel<0><<<grid, 256>>>(x, Wk, bk,  k, MROWS, UU, UU, 1.f, 0, 0, 0);
        sgemm_kernel<0><<<grid, 256>>>(x, Wv, bv,  v, MROWS, UU, UU, 1.f, 0, 0, 0);
        sgemm_kernel<0><<<grid, 256>>>(x, Wr, br_, r, MROWS, UU, UU, 1.f, 0, 0, 0);
    }

    // 2) scores = Q @ K^T / sqrt(HD)  per head (raw reshape => contiguous views)
    {
        dim3 grid(SS / BN, SS / BM, NHEAD);
        const float scale = 1.0f / sqrtf((float)HD);
        sgemm_kernel<1><<<grid, 256>>>(q, k, nullptr, sc, SS, SS, HD, scale,
                                       (size_t)SS * HD, (size_t)SS * HD, (size_t)SS * SS);
    }

    // 3) softmax over each of the 32*2048 rows
    softmax_kernel<<<NHEAD * SS, 256>>>(sc);

    // 4) attn = P @ V per head: [2048,2048] @ [2048,128]
    {
        dim3 grid(HD / BN > 0 ? HD / BN : 1, SS / BM, NHEAD);
        sgemm_kernel<2><<<grid, 256>>>(sc, v, nullptr, attn, SS, HD, SS, 1.f,
                                       (size_t)SS * SS, (size_t)SS * HD, (size_t)SS * HD);
    }

    // 5) out = gamma * LN(relu(attn + res)) + beta
    ln_kernel<<<MROWS, 256>>>(attn, r, gamma, beta, out);
}

// round 3
// speedup vs baseline: 3.1524x; 3.1524x over previous
#include <cuda_runtime.h>
#include <math.h>
#include <stdint.h>

// ---------------------------------------------------------------------------
// Problem constants
// ---------------------------------------------------------------------------
#define SS 2048
#define UU 1024
#define HD 128
#define NHEAD 32
#define MROWS 8192
#define LN_EPS 1e-8f
#define QSCALE 0.08838834764831845f   // 1/sqrt(128)

// ---------------------------------------------------------------------------
// Scratch (device globals; allocation-free rule)
// ---------------------------------------------------------------------------
__device__ float g_xr[(size_t)MROWS * UU];
__device__ float g_wt[4 * (size_t)UU * UU];
__device__ float g_q[(size_t)MROWS * UU];
__device__ float g_k[(size_t)MROWS * UU];
__device__ float g_v[(size_t)MROWS * UU];
__device__ float g_r[(size_t)MROWS * UU];
__device__ float g_attn[(size_t)MROWS * UU];
__device__ float g_scores[(size_t)NHEAD * SS * SS];   // 512 MB

// ---------------------------------------------------------------------------
// Helpers
// ---------------------------------------------------------------------------
__device__ __forceinline__ uint32_t smem_u32(const void* p) {
    uint32_t a;
    asm("{ .reg .u64 t; cvta.to.shared.u64 t, %1; cvt.u32.u64 %0, t; }" : "=r"(a) : "l"(p));
    return a;
}
__device__ __forceinline__ float rna_tf32(float v) {
    uint32_t u;
    asm("cvt.rna.tf32.f32 %0, %1;" : "=r"(u) : "f"(v));
    return __uint_as_float(u);
}

#define CP_ASYNC16(sa, g) \
    asm volatile("cp.async.cg.shared.global [%0], [%1], 16;" :: "r"(sa), "l"(g))
#define CP_COMMIT() asm volatile("cp.async.commit_group;" ::: "memory")
#define CP_WAIT1()  asm volatile("cp.async.wait_group 1;" ::: "memory")

#define MMA_TF32(d, a, b) \
    asm volatile("mma.sync.aligned.m16n8k8.row.col.f32.tf32.tf32.f32 " \
        "{%0,%1,%2,%3}, {%4,%5,%6,%7}, {%8,%9}, {%0,%1,%2,%3};" \
        : "+f"((d)[0]), "+f"((d)[1]), "+f"((d)[2]), "+f"((d)[3]) \
        : "r"((a)[0]), "r"((a)[1]), "r"((a)[2]), "r"((a)[3]), \
          "r"((b)[0]), "r"((b)[1]))

// ---------------------------------------------------------------------------
// tf32 mma.sync GEMM:  C[128,128 tile] = post( A @ op(B) )
//   A [.,K] row-major (K-major), per-CTA 128 rows.
//   BMODE 0 (NT): B [N,K] K-major  -> C = A @ B^T
//   BMODE 1 (NN): B [K,N] N-major  -> C = A @ B
// 128 threads = 4 warps (2x2), warp tile 64x64 = 4 m16 x 8 n8 mma tiles.
// BK=32 floats; 3-stage cp.async pipeline.
// SMEM: As[m][36] (bank = 4m+k, conflict-free frag reads)
//       Bs NT: [n][36]  |  Bs NN: [k][132]
// ---------------------------------------------------------------------------
#define ASTR 36
#define BSTR_NN 132
#define STAGE_WORDS 9216          // A 128*36=4608  +  B max(128*36, 32*132)=4608
#define GSMEM (3 * STAGE_WORDS * 4)

template<int BMODE, bool BIASRELU, bool CVT>
__global__ __launch_bounds__(128, 2)
void gemm_mma(const float* __restrict__ A, const float* __restrict__ B,
              const float* __restrict__ bias, float* __restrict__ C,
              int ldA, int ldB, int ldC,
              long long aB, long long bB, long long cB,
              int kIters, float scale)
{
    extern __shared__ float sm[];
    const uint32_t su = smem_u32(sm);
    const int tid = threadIdx.x, lane = tid & 31, wid = tid >> 5;
    const int g = lane >> 2, c = lane & 3;
    const int wm0 = (wid >> 1) * 64, wn0 = (wid & 1) * 64;
    const int z = blockIdx.z;
    const int gm0 = blockIdx.y * 128, gn0 = blockIdx.x * 128;

    const float* Ab = A + (size_t)z * aB + (size_t)gm0 * ldA;
    const float* Bb = B + (size_t)z * bB;

    float acc[4][8][4];
#pragma unroll
    for (int mi = 0; mi < 4; mi++)
#pragma unroll
        for (int ni = 0; ni < 8; ni++)
#pragma unroll
            for (int t = 0; t < 4; t++) acc[mi][ni][t] = 0.f;

    auto load_tile = [&](int i, int s) {
        const uint32_t abase = su + (uint32_t)(s * STAGE_WORDS) * 4;
        const uint32_t bbase = abase + 4608u * 4;
        // A: 128 rows x 8 ksegs of 16B (coalesced: 8 lanes per row)
#pragma unroll
        for (int it = 0; it < 8; it++) {
            int chunk = tid + it * 128;
            int row = chunk >> 3, ks = chunk & 7;
            CP_ASYNC16(abase + (uint32_t)(row * ASTR + ks * 4) * 4,
                       Ab + (size_t)row * ldA + i * 32 + ks * 4);
        }
        if (BMODE == 0) {
            const float* Bt = Bb + (size_t)gn0 * ldB;
#pragma unroll
            for (int it = 0; it < 8; it++) {
                int chunk = tid + it * 128;
                int row = chunk >> 3, ks = chunk & 7;
                CP_ASYNC16(bbase + (uint32_t)(row * ASTR + ks * 4) * 4,
                           Bt + (size_t)row * ldB + i * 32 + ks * 4);
            }
        } else {
#pragma unroll
            for (int it = 0; it < 8; it++) {
                int chunk = tid + it * 128;
                int row = chunk >> 5, cs = chunk & 31;   // row 0..31 (k), cs col-seg
                CP_ASYNC16(bbase + (uint32_t)(row * BSTR_NN + cs * 4) * 4,
                           Bb + (size_t)(i * 32 + row) * ldB + gn0 + cs * 4);
            }
        }
    };

    // prologue: 2 stages in flight
    load_tile(0, 0); CP_COMMIT();
    if (kIters > 1) load_tile(1, 1);
    CP_COMMIT();

    for (int i = 0; i < kIters; i++) {
        CP_WAIT1();
        __syncthreads();
        if (i + 2 < kIters) load_tile(i + 2, (i + 2) % 3);
        CP_COMMIT();

        const float* As_s = sm + (i % 3) * STAGE_WORDS;
        const float* Bs_s = As_s + 4608;

#pragma unroll
        for (int j = 0; j < 4; j++) {          // four k8 steps
            uint32_t a[4][4], b[8][2];
#pragma unroll
            for (int mi = 0; mi < 4; mi++) {
                const int m = wm0 + mi * 16 + g;
                a[mi][0] = __float_as_uint(As_s[m * ASTR + j * 8 + c]);
                a[mi][1] = __float_as_uint(As_s[(m + 8) * ASTR + j * 8 + c]);
                a[mi][2] = __float_as_uint(As_s[m * ASTR + j * 8 + c + 4]);
                a[mi][3] = __float_as_uint(As_s[(m + 8) * ASTR + j * 8 + c + 4]);
            }
#pragma unroll
            for (int ni = 0; ni < 8; ni++) {
                const int n = wn0 + ni * 8 + g;
                if (BMODE == 0) {
                    b[ni][0] = __float_as_uint(Bs_s[n * ASTR + j * 8 + c]);
                    b[ni][1] = __float_as_uint(Bs_s[n * ASTR + j * 8 + c + 4]);
                } else {
                    b[ni][0] = __float_as_uint(Bs_s[(j * 8 + c) * BSTR_NN + n]);
                    b[ni][1] = __float_as_uint(Bs_s[(j * 8 + c + 4) * BSTR_NN + n]);
                }
            }
#pragma unroll
            for (int mi = 0; mi < 4; mi++)
#pragma unroll
                for (int ni = 0; ni < 8; ni++)
                    MMA_TF32(acc[mi][ni], a[mi], b[ni]);
        }
        __syncthreads();
    }

    // ---- epilogue: direct float2 stores ----
    float* Cb = C + (size_t)z * cB;
#pragma unroll
    for (int mi = 0; mi < 4; mi++) {
        const int r0 = gm0 + wm0 + mi * 16 + g;
#pragma unroll
        for (int ni = 0; ni < 8; ni++) {
            const int col = gn0 + wn0 + ni * 8 + c * 2;
            float v0 = acc[mi][ni][0], v1 = acc[mi][ni][1];
            float v2 = acc[mi][ni][2], v3 = acc[mi][ni][3];
            if (BIASRELU) {
                float b0 = __ldg(bias + col), b1 = __ldg(bias + col + 1);
                v0 = fmaxf(v0 + b0, 0.f); v1 = fmaxf(v1 + b1, 0.f);
                v2 = fmaxf(v2 + b0, 0.f); v3 = fmaxf(v3 + b1, 0.f);
            }
            v0 *= scale; v1 *= scale; v2 *= scale; v3 *= scale;
            if (CVT) {
                v0 = rna_tf32(v0); v1 = rna_tf32(v1);
                v2 = rna_tf32(v2); v3 = rna_tf32(v3);
            }
            float2 p0 = make_float2(v0, v1), p1 = make_float2(v2, v3);
            *(float2*)(Cb + (size_t)r0 * ldC + col) = p0;
            *(float2*)(Cb + (size_t)(r0 + 8) * ldC + col) = p1;
        }
    }
}

// ---------------------------------------------------------------------------
// rna-round copy (prepares tf32 operands)
// ---------------------------------------------------------------------------
__global__ __launch_bounds__(256)
void roundx_kernel(const float* __restrict__ in, float* __restrict__ out, int n4)
{
    int i = blockIdx.x * 256 + threadIdx.x;
    if (i < n4) {
        float4 v = ((const float4*)in)[i];
        v.x = rna_tf32(v.x); v.y = rna_tf32(v.y);
        v.z = rna_tf32(v.z); v.w = rna_tf32(v.w);
        ((float4*)out)[i] = v;
    }
}

// ---------------------------------------------------------------------------
// Row softmax over 2048 columns (rounds output to tf32 for the PV GEMM)
// ---------------------------------------------------------------------------
__global__ __launch_bounds__(256)
void softmax_kernel(float* __restrict__ sc)
{
    const int tid = threadIdx.x;
    float* row = sc + (size_t)blockIdx.x * SS;

    float x[8];
    float m = -1e30f;
#pragma unroll
    for (int i = 0; i < 8; i++) { x[i] = row[tid + i * 256]; m = fmaxf(m, x[i]); }
#pragma unroll
    for (int o = 16; o > 0; o >>= 1) m = fmaxf(m, __shfl_xor_sync(0xffffffffu, m, o));
    __shared__ float sm1[8];
    if ((tid & 31) == 0) sm1[tid >> 5] = m;
    __syncthreads();
    m = sm1[0];
#pragma unroll
    for (int i = 1; i < 8; i++) m = fmaxf(m, sm1[i]);

    float s = 0.f;
#pragma unroll
    for (int i = 0; i < 8; i++) { x[i] = __expf(x[i] - m); s += x[i]; }
#pragma unroll
    for (int o = 16; o > 0; o >>= 1) s += __shfl_xor_sync(0xffffffffu, s, o);
    __shared__ float ss2[8];
    if ((tid & 31) == 0) ss2[tid >> 5] = s;
    __syncthreads();
    s = 0.f;
#pragma unroll
    for (int i = 0; i < 8; i++) s += ss2[i];

    const float inv = 1.0f / s;
#pragma unroll
    for (int i = 0; i < 8; i++) row[tid + i * 256] = rna_tf32(x[i] * inv);
}

// ---------------------------------------------------------------------------
// Fused epilogue: out = gamma * LN(relu(attn + res)) + beta
// ---------------------------------------------------------------------------
__device__ __forceinline__ float block_sum_256(float v, float* sh)
{
#pragma unroll
    for (int o = 16; o > 0; o >>= 1) v += __shfl_xor_sync(0xffffffffu, v, o);
    if ((threadIdx.x & 31) == 0) sh[threadIdx.x >> 5] = v;
    __syncthreads();
    float t = 0.f;
#pragma unroll
    for (int i = 0; i < 8; i++) t += sh[i];
    __syncthreads();
    return t;
}

__global__ __launch_bounds__(256)
void ln_kernel(const float* __restrict__ attn, const float* __restrict__ res,
               const float* __restrict__ gamma, const float* __restrict__ beta,
               float* __restrict__ out)
{
    __shared__ float sh[8];
    const int tid = threadIdx.x;
    const size_t base = (size_t)blockIdx.x * UU;

    float v[4];
    float s = 0.f;
#pragma unroll
    for (int i = 0; i < 4; i++) {
        int cidx = tid + i * 256;
        float t = fmaxf(attn[base + cidx] + res[base + cidx], 0.f);
        v[i] = t; s += t;
    }
    const float mean = block_sum_256(s, sh) * (1.0f / UU);

    float vs = 0.f;
#pragma unroll
    for (int i = 0; i < 4; i++) { float d = v[i] - mean; vs += d * d; }
    const float var = block_sum_256(vs, sh) * (1.0f / UU);
    const float inv = rsqrtf(var + LN_EPS);

#pragma unroll
    for (int i = 0; i < 4; i++) {
        int cidx = tid + i * 256;
        out[base + cidx] = gamma[cidx] * ((v[i] - mean) * inv) + beta[cidx];
    }
}

// ---------------------------------------------------------------------------
extern "C" void kernel_launch(void* const* d_in, const int* in_sizes, int n_in,
                              void* d_out, int out_size)
{
    const float* x     = (const float*)d_in[0];
    const float* Wq    = (const float*)d_in[1];
    const float* bq    = (const float*)d_in[2];
    const float* Wk    = (const float*)d_in[3];
    const float* bk    = (const float*)d_in[4];
    const float* Wv    = (const float*)d_in[5];
    const float* bv    = (const float*)d_in[6];
    const float* Wr    = (const float*)d_in[7];
    const float* br_   = (const float*)d_in[8];
    const float* gamma = (const float*)d_in[9];
    const float* beta  = (const float*)d_in[10];
    float* out = (float*)d_out;

    float *xr, *wt, *q, *k, *v, *r, *attn, *sc;
    cudaGetSymbolAddress((void**)&xr,   g_xr);
    cudaGetSymbolAddress((void**)&wt,   g_wt);
    cudaGetSymbolAddress((void**)&q,    g_q);
    cudaGetSymbolAddress((void**)&k,    g_k);
    cudaGetSymbolAddress((void**)&v,    g_v);
    cudaGetSymbolAddress((void**)&r,    g_r);
    cudaGetSymbolAddress((void**)&attn, g_attn);
    cudaGetSymbolAddress((void**)&sc,   g_scores);

    cudaFuncSetAttribute(gemm_mma<1, true,  true >, cudaFuncAttributeMaxDynamicSharedMemorySize, GSMEM);
    cudaFuncSetAttribute(gemm_mma<1, true,  false>, cudaFuncAttributeMaxDynamicSharedMemorySize, GSMEM);
    cudaFuncSetAttribute(gemm_mma<0, false, false>, cudaFuncAttributeMaxDynamicSharedMemorySize, GSMEM);
    cudaFuncSetAttribute(gemm_mma<1, false, false>, cudaFuncAttributeMaxDynamicSharedMemorySize, GSMEM);

    // 1) tf32-round x and weights (no transposes needed: NN GEMM mode)
    roundx_kernel<<<(MROWS * UU / 4 + 255) / 256, 256>>>(x, xr, MROWS * UU / 4);
    roundx_kernel<<<(UU * UU / 4 + 255) / 256, 256>>>(Wq, wt + 0 * (size_t)UU * UU, UU * UU / 4);
    roundx_kernel<<<(UU * UU / 4 + 255) / 256, 256>>>(Wk, wt + 1 * (size_t)UU * UU, UU * UU / 4);
    roundx_kernel<<<(UU * UU / 4 + 255) / 256, 256>>>(Wv, wt + 2 * (size_t)UU * UU, UU * UU / 4);
    roundx_kernel<<<(UU * UU / 4 + 255) / 256, 256>>>(Wr, wt + 3 * (size_t)UU * UU, UU * UU / 4);

    // 2) projections: C = relu(x @ W + b); q pre-scaled by 1/sqrt(HD); q/k/v rounded
    {
        dim3 gr(UU / 128, MROWS / 128, 1);
        gemm_mma<1, true, true ><<<gr, 128, GSMEM>>>(xr, wt + 0 * (size_t)UU * UU, bq,  q, UU, UU, UU, 0, 0, 0, UU / 32, QSCALE);
        gemm_mma<1, true, true ><<<gr, 128, GSMEM>>>(xr, wt + 1 * (size_t)UU * UU, bk,  k, UU, UU, UU, 0, 0, 0, UU / 32, 1.0f);
        gemm_mma<1, true, true ><<<gr, 128, GSMEM>>>(xr, wt + 2 * (size_t)UU * UU, bv,  v, UU, UU, UU, 0, 0, 0, UU / 32, 1.0f);
        gemm_mma<1, true, false><<<gr, 128, GSMEM>>>(xr, wt + 3 * (size_t)UU * UU, br_, r, UU, UU, UU, 0, 0, 0, UU / 32, 1.0f);
    }

    // 3) scores = q @ k^T per head (raw-reshape head blocks: base z*SS*HD, ld=HD)
    gemm_mma<0, false, false><<<dim3(SS / 128, SS / 128, NHEAD), 128, GSMEM>>>(
        q, k, nullptr, sc, HD, HD, SS,
        (long long)SS * HD, (long long)SS * HD, (long long)SS * SS, HD / 32, 1.0f);

    // 4) softmax (tf32-rounds P)
    softmax_kernel<<<NHEAD * SS, 256>>>(sc);

    // 5) attn = P @ V per head (NN: B = v[s][d])
    gemm_mma<1, false, false><<<dim3(1, SS / 128, NHEAD), 128, GSMEM>>>(
        sc, v, nullptr, attn, SS, HD, HD,
        (long long)SS * SS, (long long)SS * HD, (long long)SS * HD, SS / 32, 1.0f);

    // 6) out = gamma * LN(relu(attn + res)) + beta
    ln_kernel<<<MROWS, 256>>>(attn, r, gamma, beta, out);
}